// round 16
// baseline (speedup 1.0000x reference)
#include <cuda_runtime.h>
#include <cuda_bf16.h>
#include <cstdint>

#define NN 100000
#define EE 300000
#define DD 256
#define GG 4000
#define LL 5
#define F_IN 40

// ---------------- scratch (device globals: allocation-free) ----------------
__device__ float g_h[NN * DD];                     // raw (pre-BN) features
__device__ __align__(16) __nv_bfloat16 g_aggH[NN * DD];
__device__ __align__(16) __nv_bfloat16 g_aggL[NN * DD];
__device__ __align__(16) __nv_bfloat16 g_tH[NN * 2 * DD];
__device__ __align__(16) __nv_bfloat16 g_tL[NN * 2 * DD];
__device__ uint4 g_W1t[163840];
__device__ uint4 g_W2t[163840];
__device__ float g_sum[DD];
__device__ float g_sumsq[DD];
__device__ __align__(16) float g_combo[LL * 9 * DD];
__device__ __align__(16) float g_self[LL * DD];
__device__ float g_mol[GG * DD];
__device__ float g_cnt[GG];
__device__ float g_z1[GG * DD];
__device__ float g_z2[GG * DD];
// CSR (built once per call)
__device__ int g_deg[NN];
__device__ int g_rowptr[NN + 1];
__device__ int g_fill[NN];
__device__ int g_esort[EE];      // packed: src | (a0*3+a1)<<20

// ---------------- helpers ----------------
__device__ __forceinline__ void red_add_v4(float* addr, float4 v) {
    asm volatile("red.global.add.v4.f32 [%0], {%1,%2,%3,%4};"
                 :: "l"(addr), "f"(v.x), "f"(v.y), "f"(v.z), "f"(v.w)
                 : "memory");
}
__device__ __forceinline__ void ldsm4(uint32_t r[4], uint32_t addr) {
    asm volatile("ldmatrix.sync.aligned.m8n8.x4.shared.b16 {%0,%1,%2,%3}, [%4];"
        : "=r"(r[0]), "=r"(r[1]), "=r"(r[2]), "=r"(r[3]) : "r"(addr));
}
__device__ __forceinline__ void ldsm4t(uint32_t r[4], uint32_t addr) {
    asm volatile("ldmatrix.sync.aligned.m8n8.x4.trans.shared.b16 {%0,%1,%2,%3}, [%4];"
        : "=r"(r[0]), "=r"(r[1]), "=r"(r[2]), "=r"(r[3]) : "r"(addr));
}
__device__ __forceinline__ void mma16816(float c[4], const uint32_t a[4],
                                         uint32_t b0, uint32_t b1) {
    asm volatile("mma.sync.aligned.m16n8k16.row.col.f32.bf16.bf16.f32 "
        "{%0,%1,%2,%3}, {%4,%5,%6,%7}, {%8,%9}, {%0,%1,%2,%3};"
        : "+f"(c[0]), "+f"(c[1]), "+f"(c[2]), "+f"(c[3])
        : "r"(a[0]), "r"(a[1]), "r"(a[2]), "r"(a[3]), "r"(b0), "r"(b1));
}
__device__ __forceinline__ void cpa16(uint32_t dst, const void* src, uint32_t sz) {
    asm volatile("cp.async.cg.shared.global [%0], [%1], 16, %2;"
                 :: "r"(dst), "l"(src), "r"(sz) : "memory");
}

// ---------------- embed: smem-tiled, 64 nodes/block ----------------
__global__ void __launch_bounds__(256) embed_kernel(const float* __restrict__ x,
                                                    const float* __restrict__ W,
                                                    const float* __restrict__ b) {
    __shared__ float Ws[F_IN * DD];
    __shared__ float xs[64 * F_IN];
    const int tid   = threadIdx.x;
    const int node0 = blockIdx.x * 64;
    const int nNodes = min(64, NN - node0);

    for (int i = tid; i < F_IN * DD; i += 256) Ws[i] = W[i];
    for (int i = tid; i < nNodes * F_IN; i += 256) xs[i] = x[node0 * F_IN + i];
    __syncthreads();

    const float bias = b[tid];
    for (int n = 0; n < nNodes; n += 4) {
        float a0 = bias, a1 = bias, a2 = bias, a3 = bias;
#pragma unroll
        for (int k = 0; k < F_IN; k++) {
            float w = Ws[k * DD + tid];
            a0 = fmaf(xs[(n + 0) * F_IN + k], w, a0);
            a1 = fmaf(xs[(n + 1) * F_IN + k], w, a1);
            a2 = fmaf(xs[(n + 2) * F_IN + k], w, a2);
            a3 = fmaf(xs[(n + 3) * F_IN + k], w, a3);
        }
        g_h[(size_t)(node0 + n + 0) * DD + tid] = fmaxf(a0, 0.f);
        g_h[(size_t)(node0 + n + 1) * DD + tid] = fmaxf(a1, 0.f);
        g_h[(size_t)(node0 + n + 2) * DD + tid] = fmaxf(a2, 0.f);
        g_h[(size_t)(node0 + n + 3) * DD + tid] = fmaxf(a3, 0.f);
    }
}

// ---------------- fused init: deg, cnt, mol ----------------
__global__ void init_kernel() {
    int i = blockIdx.x * 256 + threadIdx.x;
    if (i < NN) g_deg[i] = 0;
    if (i < GG) g_cnt[i] = 0.f;
    if (i < GG * DD) g_mol[i] = 0.f;
}

// ---------------- CSR build ----------------
__global__ void hist_kernel(const int* __restrict__ dst) {
    int e = blockIdx.x * 256 + threadIdx.x;
    if (e < EE) atomicAdd(&g_deg[dst[e]], 1);
}
__global__ void scan_kernel() {
    __shared__ int ss[1024];
    int t = threadIdx.x;
    const int chunk = (NN + 1023) / 1024;
    int s0 = t * chunk;
    int s1 = min(s0 + chunk, NN);
    int s = 0;
    for (int i = s0; i < s1; i++) s += g_deg[i];
    ss[t] = s;
    __syncthreads();
    for (int d = 1; d < 1024; d <<= 1) {
        int v = (t >= d) ? ss[t - d] : 0;
        __syncthreads();
        ss[t] += v;
        __syncthreads();
    }
    int off = ss[t] - s;
    for (int i = s0; i < s1; i++) {
        g_rowptr[i] = off;
        g_fill[i]   = off;
        off += g_deg[i];
    }
    if (t == 1023) g_rowptr[NN] = ss[1023];
}
__global__ void fill_kernel(const int* __restrict__ src,
                            const int* __restrict__ dst,
                            const int* __restrict__ eattr) {
    int e = blockIdx.x * 256 + threadIdx.x;
    if (e >= EE) return;
    int pos = atomicAdd(&g_fill[dst[e]], 1);
    int ci  = eattr[2 * e] * 3 + eattr[2 * e + 1];
    g_esort[pos] = src[e] | (ci << 20);
}

// ---------------- combo table prep ----------------
__global__ void prep_combo(const float* __restrict__ ee1,
                           const float* __restrict__ ee2) {
    int ci = blockIdx.x;
    int l  = blockIdx.y;
    int d  = threadIdx.x;
    int a0 = ci / 3, a1 = ci % 3;
    g_combo[((size_t)l * 9 + ci) * DD + d] =
        ee1[((size_t)l * 6 + a0) * DD + d] + ee2[((size_t)l * 3 + a1) * DD + d];
    if (ci == 0)
        g_self[(size_t)l * DD + d] =
            ee1[((size_t)l * 6 + 4) * DD + d] + ee2[(size_t)l * 3 * DD + d];
}

// ------- fused aggregate: inline BN coefs, prefetched edge records ----------
__global__ void __launch_bounds__(256) agg_kernel(const float* __restrict__ combo,
                                                  const float* __restrict__ selfadd,
                                                  int useBN,
                                                  const float* __restrict__ gamma,
                                                  const float* __restrict__ beta) {
    int node = blockIdx.x * 4 + (threadIdx.x >> 6);
    int c    = threadIdx.x & 63;
    int lane = threadIdx.x & 31;
    if (node >= NN) return;
    const float4* h4 = (const float4*)g_h;
    const float4* cb4 = (const float4*)combo;

    float4 av = make_float4(1.f, 1.f, 1.f, 1.f);
    float4 cv = make_float4(0.f, 0.f, 0.f, 0.f);
    if (useBN) {
        const float invN = 1.f / (float)NN;
        float4 s = ((const float4*)g_sum)[c];
        float4 q = ((const float4*)g_sumsq)[c];
        float4 gm = ((const float4*)gamma)[c];
        float4 bt = ((const float4*)beta)[c];
        float mux = s.x * invN, muy = s.y * invN, muz = s.z * invN, muw = s.w * invN;
        av.x = gm.x * rsqrtf(q.x * invN - mux * mux + 1e-5f);
        av.y = gm.y * rsqrtf(q.y * invN - muy * muy + 1e-5f);
        av.z = gm.z * rsqrtf(q.z * invN - muz * muz + 1e-5f);
        av.w = gm.w * rsqrtf(q.w * invN - muw * muw + 1e-5f);
        cv.x = bt.x - mux * av.x;
        cv.y = bt.y - muy * av.y;
        cv.z = bt.z - muz * av.z;
        cv.w = bt.w - muw * av.w;
    }

    float4 v = h4[(size_t)node * 64 + c];
    float4 acc;
    if (useBN) {
        acc.x = fmaxf(fmaf(av.x, v.x, cv.x), 0.f);
        acc.y = fmaxf(fmaf(av.y, v.y, cv.y), 0.f);
        acc.z = fmaxf(fmaf(av.z, v.z, cv.z), 0.f);
        acc.w = fmaxf(fmaf(av.w, v.w, cv.w), 0.f);
    } else {
        acc = v;
    }
    {
        float4 t = ((const float4*)selfadd)[c];
        acc.x += t.x; acc.y += t.y; acc.z += t.z; acc.w += t.w;
    }

    int p0 = g_rowptr[node], p1 = g_rowptr[node + 1];
    int p = p0;
    int rec = (p0 + lane < p1) ? g_esort[p0 + lane] : 0;
    while (p < p1) {
        int cnt = min(32, p1 - p);
        int cur = rec;
        if (p + 32 < p1)
            rec = (p + 32 + lane < p1) ? g_esort[p + 32 + lane] : 0;
        for (int j = 0; j < cnt; j++) {
            int r  = __shfl_sync(0xFFFFFFFFu, cur, j);
            int s  = r & 0xFFFFF;
            int ci = r >> 20;
            float4 w = h4[(size_t)s * 64 + c];
            if (useBN) {
                w.x = fmaxf(fmaf(av.x, w.x, cv.x), 0.f);
                w.y = fmaxf(fmaf(av.y, w.y, cv.y), 0.f);
                w.z = fmaxf(fmaf(av.z, w.z, cv.z), 0.f);
                w.w = fmaxf(fmaf(av.w, w.w, cv.w), 0.f);
            }
            float4 u = cb4[(size_t)ci * 64 + c];
            acc.x += w.x + u.x;
            acc.y += w.y + u.y;
            acc.z += w.z + u.z;
            acc.w += w.w + u.w;
        }
        p += cnt;
    }

    __nv_bfloat16 hx = __float2bfloat16(acc.x), hy = __float2bfloat16(acc.y);
    __nv_bfloat16 hz = __float2bfloat16(acc.z), hw = __float2bfloat16(acc.w);
    __nv_bfloat162 h0(hx, hy), h1(hz, hw);
    __nv_bfloat162 l0(__float2bfloat16(acc.x - __bfloat162float(hx)),
                      __float2bfloat16(acc.y - __bfloat162float(hy)));
    __nv_bfloat162 l1(__float2bfloat16(acc.z - __bfloat162float(hz)),
                      __float2bfloat16(acc.w - __bfloat162float(hw)));
    uint2 h, l;
    h.x = *(uint32_t*)&h0; h.y = *(uint32_t*)&h1;
    l.x = *(uint32_t*)&l0; l.y = *(uint32_t*)&l1;
    *(uint2*)(g_aggH + (size_t)node * DD + c * 4) = h;
    *(uint2*)(g_aggL + (size_t)node * DD + c * 4) = l;
}

// ---------------- weight prep ----------------
__global__ void prep_w(const float* __restrict__ W, uint4* __restrict__ dst,
                       int Nc, int ktiles) {
    int cb = blockIdx.x, kt = blockIdx.y, l = blockIdx.z;
    const float* Wl = W + (size_t)l * (ktiles * 32) * Nc;
    char* blob = (char*)dst + (((size_t)l * gridDim.x + cb) * ktiles + kt) * 16384;
    for (int e = threadIdx.x; e < 4096; e += 256) {
        int k = e >> 7, n = e & 127;
        float v = Wl[(size_t)(kt * 32 + k) * Nc + cb * 128 + n];
        __nv_bfloat16 h = __float2bfloat16(v);
        __nv_bfloat16 lo = __float2bfloat16(v - __bfloat162float(h));
        uint32_t off = k * 256 + n * 2;
        uint32_t sw = off ^ ((k & 7) << 4);
        *(__nv_bfloat16*)(blob + sw) = h;
        *(__nv_bfloat16*)(blob + 8192 + sw) = lo;
    }
}

// ====== tensor-core GEMM, bf16 3-way split, 3-stage cp.async, occ 2 ======
#define STAGE 32768
#define NSTAGE 3
#define P_AH 0
#define P_AL 8192
#define P_BH 16384
#define P_BL 24576

template <int OUT>
__global__ void __launch_bounds__(256, 2) gemm_cp(
    const __nv_bfloat16* __restrict__ AH, const __nv_bfloat16* __restrict__ AL,
    const char* __restrict__ Btiles, const float* __restrict__ bias,
    float* __restrict__ Cf, __nv_bfloat16* __restrict__ CH,
    __nv_bfloat16* __restrict__ CL, int M, int K, int Nc) {
    extern __shared__ __align__(16) char sm[];
    const int tid  = threadIdx.x;
    const int lane = tid & 31;
    const int warp = tid >> 5;
    const int wm   = warp >> 1;
    const int wn   = warp & 1;
    const int row0 = blockIdx.y * 128;
    const int col0 = blockIdx.x * 128;
    const int ktiles = K >> 5;

    if (OUT == 1 && blockIdx.x == 0 && blockIdx.y == 0) {
        g_sum[tid]   = 0.f;
        g_sumsq[tid] = 0.f;
    }

    uint32_t smbase;
    asm("{ .reg .u64 t; cvta.to.shared.u64 t, %1; cvt.u32.u64 %0, t; }"
        : "=r"(smbase) : "l"(sm));

    const int m0 = tid >> 2, kq0 = tid & 3;
    const int m1 = (tid + 256) >> 2, kq1 = (tid + 256) & 3;
    const uint32_t dA0 = (uint32_t)(m0 * 64 + kq0 * 16) ^ ((m0 & 6) << 3);
    const uint32_t dA1 = (uint32_t)(m1 * 64 + kq1 * 16) ^ ((m1 & 6) << 3);
    const uint32_t ok0 = (row0 + m0 < M) ? 16u : 0u;
    const uint32_t ok1 = (row0 + m1 < M) ? 16u : 0u;
    const __nv_bfloat16* sH0 = AH + (size_t)(row0 + m0) * K + kq0 * 8;
    const __nv_bfloat16* sH1 = AH + (size_t)(row0 + m1) * K + kq1 * 8;
    const __nv_bfloat16* sL0 = AL + (size_t)(row0 + m0) * K + kq0 * 8;
    const __nv_bfloat16* sL1 = AL + (size_t)(row0 + m1) * K + kq1 * 8;
    const char* tbase = Btiles + (size_t)blockIdx.x * ktiles * 16384;

    float acc[2][8][4];
#pragma unroll
    for (int mi = 0; mi < 2; mi++)
#pragma unroll
        for (int nt = 0; nt < 8; nt++)
#pragma unroll
            for (int q = 0; q < 4; q++) acc[mi][nt][q] = 0.f;

#define ISSUE(kt, st) do {                                                    \
        uint32_t sb = smbase + (st) * STAGE;                                  \
        int ko = (kt) * 32;                                                   \
        cpa16(sb + P_AH + dA0, sH0 + ko, ok0);                                \
        cpa16(sb + P_AH + dA1, sH1 + ko, ok1);                                \
        cpa16(sb + P_AL + dA0, sL0 + ko, ok0);                                \
        cpa16(sb + P_AL + dA1, sL1 + ko, ok1);                                \
        const char* tb = tbase + (size_t)(kt) * 16384;                        \
        cpa16(sb + P_BH + tid * 16,        tb + tid * 16, 16);                \
        cpa16(sb + P_BH + tid * 16 + 4096, tb + tid * 16 + 4096, 16);         \
        cpa16(sb + P_BL + tid * 16,        tb + 8192 + tid * 16, 16);         \
        cpa16(sb + P_BL + tid * 16 + 4096, tb + 12288 + tid * 16, 16);        \
        asm volatile("cp.async.commit_group;" ::: "memory");                  \
    } while (0)

    ISSUE(0, 0);
    if (ktiles > 1) ISSUE(1, 1);

    int stage = 0;
    for (int kt = 0; kt < ktiles; kt++) {
        if (kt + 1 < ktiles) {
            asm volatile("cp.async.wait_group 1;" ::: "memory");
        } else {
            asm volatile("cp.async.wait_group 0;" ::: "memory");
        }
        __syncthreads();

        if (kt + 2 < ktiles) {
            int nst = stage + 2;
            if (nst >= NSTAGE) nst -= NSTAGE;
            ISSUE(kt + 2, nst);
        }

        const uint32_t cbase = smbase + stage * STAGE;
#pragma unroll
        for (int ks = 0; ks < 2; ks++) {
            uint32_t a_h[2][4], a_l[2][4];
#pragma unroll
            for (int mi = 0; mi < 2; mi++) {
                int m = wm * 32 + mi * 16 + (lane & 15);
                int k = ks * 16 + (lane >> 4) * 8;
                uint32_t byte = (uint32_t)(m * 64 + k * 2) ^ ((m & 6) << 3);
                ldsm4(a_h[mi], cbase + P_AH + byte);
                ldsm4(a_l[mi], cbase + P_AL + byte);
            }
#pragma unroll
            for (int nj = 0; nj < 4; nj++) {
                int k = ks * 16 + (lane & 15);
                int n = wn * 64 + nj * 16 + (lane >> 4) * 8;
                uint32_t byte = (uint32_t)(k * 256 + n * 2) ^ ((k & 7) << 4);
                uint32_t bh[4], bl[4];
                ldsm4t(bh, cbase + P_BH + byte);
                ldsm4t(bl, cbase + P_BL + byte);
#pragma unroll
                for (int mi = 0; mi < 2; mi++) {
                    mma16816(acc[mi][2 * nj],     a_h[mi], bh[0], bh[1]);
                    mma16816(acc[mi][2 * nj],     a_h[mi], bl[0], bl[1]);
                    mma16816(acc[mi][2 * nj],     a_l[mi], bh[0], bh[1]);
                    mma16816(acc[mi][2 * nj + 1], a_h[mi], bh[2], bh[3]);
                    mma16816(acc[mi][2 * nj + 1], a_h[mi], bl[2], bl[3]);
                    mma16816(acc[mi][2 * nj + 1], a_l[mi], bh[2], bh[3]);
                }
            }
        }
        if (++stage >= NSTAGE) stage = 0;
    }
#undef ISSUE

    if (OUT == 1) {
#pragma unroll
        for (int mi = 0; mi < 2; mi++) {
            int r0 = row0 + wm * 32 + mi * 16 + (lane >> 2);
#pragma unroll
            for (int nt = 0; nt < 8; nt++) {
                int c = col0 + wn * 64 + nt * 8 + (lane & 3) * 2;
                float2 bv = *(const float2*)(bias + c);
                float* a4 = acc[mi][nt];
#pragma unroll
                for (int half = 0; half < 2; half++) {
                    int r = r0 + half * 8;
                    if (r < M) {
                        float v0 = fmaxf(a4[2 * half + 0] + bv.x, 0.f);
                        float v1 = fmaxf(a4[2 * half + 1] + bv.y, 0.f);
                        __nv_bfloat16 h0 = __float2bfloat16(v0);
                        __nv_bfloat16 h1 = __float2bfloat16(v1);
                        __nv_bfloat162 hp(h0, h1);
                        __nv_bfloat162 lp(__float2bfloat16(v0 - __bfloat162float(h0)),
                                          __float2bfloat16(v1 - __bfloat162float(h1)));
                        *(__nv_bfloat162*)(CH + (size_t)r * Nc + c) = hp;
                        *(__nv_bfloat162*)(CL + (size_t)r * Nc + c) = lp;
                    }
                }
            }
        }
    } else {
        float cs[16], cq[16];
#pragma unroll
        for (int j = 0; j < 16; j++) { cs[j] = 0.f; cq[j] = 0.f; }
#pragma unroll
        for (int mi = 0; mi < 2; mi++) {
            int r0 = row0 + wm * 32 + mi * 16 + (lane >> 2);
#pragma unroll
            for (int nt = 0; nt < 8; nt++) {
                int c = col0 + wn * 64 + nt * 8 + (lane & 3) * 2;
                float2 bv = *(const float2*)(bias + c);
                float* a4 = acc[mi][nt];
#pragma unroll
                for (int half = 0; half < 2; half++) {
                    int r = r0 + half * 8;
                    if (r < M) {
                        float v0 = a4[2 * half + 0] + bv.x;
                        float v1 = a4[2 * half + 1] + bv.y;
                        float2 o; o.x = v0; o.y = v1;
                        *(float2*)(Cf + (size_t)r * Nc + c) = o;
                        cs[nt * 2 + 0] += v0; cq[nt * 2 + 0] += v0 * v0;
                        cs[nt * 2 + 1] += v1; cq[nt * 2 + 1] += v1 * v1;
                    }
                }
            }
        }
#pragma unroll
        for (int j = 0; j < 16; j++) {
#pragma unroll
            for (int msk = 4; msk <= 16; msk <<= 1) {
                cs[j] += __shfl_xor_sync(0xFFFFFFFF, cs[j], msk);
                cq[j] += __shfl_xor_sync(0xFFFFFFFF, cq[j], msk);
            }
        }
        float* ssum = (float*)sm;
        float* ssq  = ssum + 128;
        __syncthreads();
        if (tid < 128) { ssum[tid] = 0.f; ssq[tid] = 0.f; }
        __syncthreads();
        if ((lane >> 2) == 0) {
#pragma unroll
            for (int j = 0; j < 16; j++) {
                int cl = wn * 64 + (j >> 1) * 8 + (lane & 3) * 2 + (j & 1);
                atomicAdd(&ssum[cl], cs[j]);
                atomicAdd(&ssq[cl],  cq[j]);
            }
        }
        __syncthreads();
        if (tid < 128) {
            atomicAdd(&g_sum[col0 + tid],   ssum[tid]);
            atomicAdd(&g_sumsq[col0 + tid], ssq[tid]);
        }
    }
}

// ---------------- small GEMM (head MLP), optional per-row scale ----------
template <int RELU>
__global__ void __launch_bounds__(256) gemm_bias(const float* __restrict__ A,
                                                 const float* __restrict__ B,
                                                 const float* __restrict__ bias,
                                                 float* __restrict__ C,
                                                 int M, int K, int Nc,
                                                 const float* __restrict__ rowcnt) {
    __shared__ float As[16][64];
    __shared__ float Bs[16][64];

    int tid  = threadIdx.x;
    int row0 = blockIdx.y * 64;
    int col0 = blockIdx.x * 64;
    int ty   = tid >> 4;
    int tx   = tid & 15;

    int ar = tid >> 2;
    int ak = (tid & 3) * 4;
    int bk = tid >> 4;
    int bc = (tid & 15) * 4;

    float acc[4][4];
#pragma unroll
    for (int i = 0; i < 4; i++)
#pragma unroll
        for (int j = 0; j < 4; j++) acc[i][j] = 0.f;

    int arow = row0 + ar;
    int bcol = col0 + bc;
    float rs = 1.f;
    if (rowcnt && arow < M) rs = 1.f / fmaxf(rowcnt[arow], 1.f);

    for (int k0 = 0; k0 < K; k0 += 16) {
        float4 av = make_float4(0.f, 0.f, 0.f, 0.f);
        if (arow < M)
            av = *(const float4*)(A + (size_t)arow * K + k0 + ak);
        As[ak + 0][ar] = av.x * rs;
        As[ak + 1][ar] = av.y * rs;
        As[ak + 2][ar] = av.z * rs;
        As[ak + 3][ar] = av.w * rs;

        float4 bv = make_float4(0.f, 0.f, 0.f, 0.f);
        if (bcol < Nc)
            bv = *(const float4*)(B + (size_t)(k0 + bk) * Nc + bcol);
        *(float4*)(&Bs[bk][bc]) = bv;

        __syncthreads();
#pragma unroll
        for (int k = 0; k < 16; k++) {
            float4 a4 = *(const float4*)(&As[k][ty * 4]);
            float4 b4 = *(const float4*)(&Bs[k][tx * 4]);
            float a[4] = {a4.x, a4.y, a4.z, a4.w};
            float b[4] = {b4.x, b4.y, b4.z, b4.w};
#pragma unroll
            for (int i = 0; i < 4; i++)
#pragma unroll
                for (int j = 0; j < 4; j++)
                    acc[i][j] = fmaf(a[i], b[j], acc[i][j]);
        }
        __syncthreads();
    }

#pragma unroll
    for (int i = 0; i < 4; i++) {
        int r = row0 + ty * 4 + i;
        if (r < M) {
#pragma unroll
            for (int j = 0; j < 4; j++) {
                int c = col0 + tx * 4 + j;
                if (c < Nc) {
                    float v = acc[i][j] + bias[c];
                    if (RELU) v = fmaxf(v, 0.f);
                    C[(size_t)r * Nc + c] = v;
                }
            }
        }
    }
}

// ---------------- pooling (inline last-layer BN affine, no relu) ----------
__global__ void count_kernel(const int* __restrict__ batch) {
    int i = blockIdx.x * 256 + threadIdx.x;
    if (i < NN) atomicAdd(&g_cnt[batch[i]], 1.f);
}

__global__ void pool_scatter_kernel(const int* __restrict__ batch,
                                    const float* __restrict__ gamma,
                                    const float* __restrict__ beta) {
    int n = blockIdx.x * 4 + (threadIdx.x >> 6);
    int c = threadIdx.x & 63;
    if (n >= NN) return;
    const float invN = 1.f / (float)NN;
    float4 s = ((const float4*)g_sum)[c];
    float4 q = ((const float4*)g_sumsq)[c];
    float4 gm = ((const float4*)gamma)[c];
    float4 bt = ((const float4*)beta)[c];
    float mux = s.x * invN, muy = s.y * invN, muz = s.z * invN, muw = s.w * invN;
    float ax = gm.x * rsqrtf(q.x * invN - mux * mux + 1e-5f);
    float ay = gm.y * rsqrtf(q.y * invN - muy * muy + 1e-5f);
    float az = gm.z * rsqrtf(q.z * invN - muz * muz + 1e-5f);
    float aw = gm.w * rsqrtf(q.w * invN - muw * muw + 1e-5f);
    float cx = bt.x - mux * ax, cy = bt.y - muy * ay;
    float cz = bt.z - muz * az, cw = bt.w - muw * aw;

    int g = batch[n];
    float4 v = ((const float4*)(g_h + (size_t)n * DD))[c];
    v.x = fmaf(ax, v.x, cx);
    v.y = fmaf(ay, v.y, cy);
    v.z = fmaf(az, v.z, cz);
    v.w = fmaf(aw, v.w, cw);
    red_add_v4(g_mol + (size_t)g * DD + c * 4, v);
}

// ---------------- head final ----------------
__global__ void head_final_kernel(const float* __restrict__ w,
                                  const float* __restrict__ b,
                                  float* __restrict__ out) {
    int g = blockIdx.x * 256 + threadIdx.x;
    if (g >= GG) return;
    float acc = b[0];
#pragma unroll
    for (int k = 0; k < 32; k++)
        acc = fmaf(g_z2[g * 32 + k], w[k], acc);
    out[g] = acc;
}

// ---------------- launch ----------------
extern "C" void kernel_launch(void* const* d_in, const int* in_sizes, int n_in,
                              void* d_out, int out_size) {
    const float* x          = (const float*)d_in[0];
    const int*   edge_index = (const int*)d_in[1];
    const int*   edge_attr  = (const int*)d_in[2];
    const int*   batch      = (const int*)d_in[3];
    const float* embW       = (const float*)d_in[4];
    const float* embB       = (const float*)d_in[5];
    const float* ee1        = (const float*)d_in[6];
    const float* ee2        = (const float*)d_in[7];
    const float* W1         = (const float*)d_in[8];
    const float* b1         = (const float*)d_in[9];
    const float* W2         = (const float*)d_in[10];
    const float* b2         = (const float*)d_in[11];
    const float* bn_g       = (const float*)d_in[12];
    const float* bn_b       = (const float*)d_in[13];
    const float* hW0 = (const float*)d_in[14];
    const float* hb0 = (const float*)d_in[15];
    const float* hW1 = (const float*)d_in[16];
    const float* hb1 = (const float*)d_in[17];
    const float* hW2 = (const float*)d_in[18];
    const float* hb2 = (const float*)d_in[19];
    const float* hW3 = (const float*)d_in[20];
    const float* hb3 = (const float*)d_in[21];
    const float* hWo = (const float*)d_in[22];
    const float* hbo = (const float*)d_in[23];
    float* out = (float*)d_out;

    const int* src = edge_index;
    const int* dst = edge_index + EE;

    float *p_h, *p_mol, *p_z1, *p_z2, *p_combo, *p_self, *p_cnt;
    __nv_bfloat16 *p_aggH, *p_aggL, *p_tH, *p_tL;
    uint4 *p_W1t, *p_W2t;
    cudaGetSymbolAddress((void**)&p_h,     g_h);
    cudaGetSymbolAddress((void**)&p_mol,   g_mol);
    cudaGetSymbolAddress((void**)&p_z1,    g_z1);
    cudaGetSymbolAddress((void**)&p_z2,    g_z2);
    cudaGetSymbolAddress((void**)&p_aggH,  g_aggH);
    cudaGetSymbolAddress((void**)&p_aggL,  g_aggL);
    cudaGetSymbolAddress((void**)&p_tH,    g_tH);
    cudaGetSymbolAddress((void**)&p_tL,    g_tL);
    cudaGetSymbolAddress((void**)&p_W1t,   g_W1t);
    cudaGetSymbolAddress((void**)&p_W2t,   g_W2t);
    cudaGetSymbolAddress((void**)&p_combo, g_combo);
    cudaGetSymbolAddress((void**)&p_self,  g_self);
    cudaGetSymbolAddress((void**)&p_cnt,   g_cnt);

    static int smem_set = 0;
    if (!smem_set) {
        cudaFuncSetAttribute(gemm_cp<1>, cudaFuncAttributeMaxDynamicSharedMemorySize, NSTAGE * STAGE);
        cudaFuncSetAttribute(gemm_cp<0>, cudaFuncAttributeMaxDynamicSharedMemorySize, NSTAGE * STAGE);
        smem_set = 1;
    }

    const int rowBlocks = (NN + 127) / 128;

    // weight prep + combo tables + CSR build (once per call)
    prep_w<<<dim3(4, 8, 5),  256>>>(W1, p_W1t, 512, 8);
    prep_w<<<dim3(2, 16, 5), 256>>>(W2, p_W2t, 256, 16);
    prep_combo<<<dim3(9, 5), 256>>>(ee1, ee2);
    init_kernel<<<(GG * DD + 255) / 256, 256>>>();
    hist_kernel<<<(EE + 255) / 256, 256>>>(dst);
    scan_kernel<<<1, 1024>>>();
    fill_kernel<<<(EE + 255) / 256, 256>>>(src, dst, edge_attr);
    count_kernel<<<(NN + 255) / 256, 256>>>(batch);

    embed_kernel<<<(NN + 63) / 64, 256>>>(x, embW, embB);

    for (int l = 0; l < LL; l++) {
        agg_kernel<<<(NN + 3) / 4, 256>>>(p_combo + (size_t)l * 9 * DD,
                                          p_self + (size_t)l * DD,
                                          l > 0 ? 1 : 0,
                                          bn_g + (size_t)(l > 0 ? l - 1 : 0) * DD,
                                          bn_b + (size_t)(l > 0 ? l - 1 : 0) * DD);
        gemm_cp<1><<<dim3(4, rowBlocks), 256, NSTAGE * STAGE>>>(
            p_aggH, p_aggL, (const char*)p_W1t + (size_t)l * 4 * 8 * 16384,
            b1 + (size_t)l * 2 * DD, nullptr, p_tH, p_tL, NN, DD, 2 * DD);
        gemm_cp<0><<<dim3(2, rowBlocks), 256, NSTAGE * STAGE>>>(
            p_tH, p_tL, (const char*)p_W2t + (size_t)l * 2 * 16 * 16384,
            b2 + (size_t)l * DD, p_h, nullptr, nullptr, NN, 2 * DD, DD);
    }

    pool_scatter_kernel<<<(NN + 3) / 4, 256>>>(batch,
                                               bn_g + (size_t)(LL - 1) * DD,
                                               bn_b + (size_t)(LL - 1) * DD);

    // head MLP: mean division folded into first gemm's A-load
    gemm_bias<1><<<dim3(4, (GG + 63) / 64), 256>>>(p_mol, hW0, hb0, p_z1, GG, 256, 256, p_cnt);
    gemm_bias<1><<<dim3(2, (GG + 63) / 64), 256>>>(p_z1,  hW1, hb1, p_z2, GG, 256, 128, nullptr);
    gemm_bias<1><<<dim3(1, (GG + 63) / 64), 256>>>(p_z2,  hW2, hb2, p_z1, GG, 128, 64, nullptr);
    gemm_bias<1><<<dim3(1, (GG + 63) / 64), 256>>>(p_z1,  hW3, hb3, p_z2, GG, 64, 32, nullptr);
    head_final_kernel<<<(GG + 255) / 256, 256>>>(hWo, hbo, out);
}

// round 17
// speedup vs baseline: 1.0445x; 1.0445x over previous
#include <cuda_runtime.h>
#include <cuda_bf16.h>
#include <cstdint>

#define NN 100000
#define EE 300000
#define DD 256
#define GG 4000
#define LL 5
#define F_IN 40

// ---------------- scratch (device globals: allocation-free) ----------------
__device__ float g_h[NN * DD];                     // raw (pre-BN) features
__device__ __align__(16) __nv_bfloat16 g_aggH[NN * DD];
__device__ __align__(16) __nv_bfloat16 g_aggL[NN * DD];
__device__ __align__(16) __nv_bfloat16 g_tH[NN * 2 * DD];
__device__ __align__(16) __nv_bfloat16 g_tL[NN * 2 * DD];
__device__ uint4 g_W1t[163840];
__device__ uint4 g_W2t[163840];
__device__ float g_sum[DD];
__device__ float g_sumsq[DD];
__device__ __align__(16) float g_combo[LL * 9 * DD];
__device__ __align__(16) float g_self[LL * DD];
__device__ float g_mol[GG * DD];
__device__ float g_cnt[GG];
__device__ float g_z1[GG * DD];
__device__ float g_z2[GG * DD];
// CSR (built once per call)
__device__ int g_deg[NN];
__device__ int g_rowptr[NN + 1];
__device__ int g_fill[NN];
__device__ int g_esort[EE];      // packed: src | (a0*3+a1)<<20

// ---------------- helpers ----------------
__device__ __forceinline__ void red_add_v4(float* addr, float4 v) {
    asm volatile("red.global.add.v4.f32 [%0], {%1,%2,%3,%4};"
                 :: "l"(addr), "f"(v.x), "f"(v.y), "f"(v.z), "f"(v.w)
                 : "memory");
}
__device__ __forceinline__ void ldsm4(uint32_t r[4], uint32_t addr) {
    asm volatile("ldmatrix.sync.aligned.m8n8.x4.shared.b16 {%0,%1,%2,%3}, [%4];"
        : "=r"(r[0]), "=r"(r[1]), "=r"(r[2]), "=r"(r[3]) : "r"(addr));
}
__device__ __forceinline__ void ldsm4t(uint32_t r[4], uint32_t addr) {
    asm volatile("ldmatrix.sync.aligned.m8n8.x4.trans.shared.b16 {%0,%1,%2,%3}, [%4];"
        : "=r"(r[0]), "=r"(r[1]), "=r"(r[2]), "=r"(r[3]) : "r"(addr));
}
__device__ __forceinline__ void mma16816(float c[4], const uint32_t a[4],
                                         uint32_t b0, uint32_t b1) {
    asm volatile("mma.sync.aligned.m16n8k16.row.col.f32.bf16.bf16.f32 "
        "{%0,%1,%2,%3}, {%4,%5,%6,%7}, {%8,%9}, {%0,%1,%2,%3};"
        : "+f"(c[0]), "+f"(c[1]), "+f"(c[2]), "+f"(c[3])
        : "r"(a[0]), "r"(a[1]), "r"(a[2]), "r"(a[3]), "r"(b0), "r"(b1));
}
__device__ __forceinline__ void cpa16(uint32_t dst, const void* src, uint32_t sz) {
    asm volatile("cp.async.cg.shared.global [%0], [%1], 16, %2;"
                 :: "r"(dst), "l"(src), "r"(sz) : "memory");
}

// ---------------- embed: smem-tiled, 64 nodes/block ----------------
__global__ void __launch_bounds__(256) embed_kernel(const float* __restrict__ x,
                                                    const float* __restrict__ W,
                                                    const float* __restrict__ b) {
    __shared__ float Ws[F_IN * DD];
    __shared__ float xs[64 * F_IN];
    const int tid   = threadIdx.x;
    const int node0 = blockIdx.x * 64;
    const int nNodes = min(64, NN - node0);

    for (int i = tid; i < F_IN * DD; i += 256) Ws[i] = W[i];
    for (int i = tid; i < nNodes * F_IN; i += 256) xs[i] = x[node0 * F_IN + i];
    __syncthreads();

    const float bias = b[tid];
    for (int n = 0; n < nNodes; n += 4) {
        float a0 = bias, a1 = bias, a2 = bias, a3 = bias;
#pragma unroll
        for (int k = 0; k < F_IN; k++) {
            float w = Ws[k * DD + tid];
            a0 = fmaf(xs[(n + 0) * F_IN + k], w, a0);
            a1 = fmaf(xs[(n + 1) * F_IN + k], w, a1);
            a2 = fmaf(xs[(n + 2) * F_IN + k], w, a2);
            a3 = fmaf(xs[(n + 3) * F_IN + k], w, a3);
        }
        g_h[(size_t)(node0 + n + 0) * DD + tid] = fmaxf(a0, 0.f);
        g_h[(size_t)(node0 + n + 1) * DD + tid] = fmaxf(a1, 0.f);
        g_h[(size_t)(node0 + n + 2) * DD + tid] = fmaxf(a2, 0.f);
        g_h[(size_t)(node0 + n + 3) * DD + tid] = fmaxf(a3, 0.f);
    }
}

// ---------------- fused init: deg, cnt, mol ----------------
__global__ void init_kernel() {
    int i = blockIdx.x * 256 + threadIdx.x;
    if (i < NN) g_deg[i] = 0;
    if (i < GG) g_cnt[i] = 0.f;
    if (i < GG * DD) g_mol[i] = 0.f;
}

// ---------------- CSR build ----------------
__global__ void hist_kernel(const int* __restrict__ dst) {
    int e = blockIdx.x * 256 + threadIdx.x;
    if (e < EE) atomicAdd(&g_deg[dst[e]], 1);
}
__global__ void scan_kernel() {
    __shared__ int ss[1024];
    int t = threadIdx.x;
    const int chunk = (NN + 1023) / 1024;
    int s0 = t * chunk;
    int s1 = min(s0 + chunk, NN);
    int s = 0;
    for (int i = s0; i < s1; i++) s += g_deg[i];
    ss[t] = s;
    __syncthreads();
    for (int d = 1; d < 1024; d <<= 1) {
        int v = (t >= d) ? ss[t - d] : 0;
        __syncthreads();
        ss[t] += v;
        __syncthreads();
    }
    int off = ss[t] - s;
    for (int i = s0; i < s1; i++) {
        g_rowptr[i] = off;
        g_fill[i]   = off;
        off += g_deg[i];
    }
    if (t == 1023) g_rowptr[NN] = ss[1023];
}
__global__ void fill_kernel(const int* __restrict__ src,
                            const int* __restrict__ dst,
                            const int* __restrict__ eattr) {
    int e = blockIdx.x * 256 + threadIdx.x;
    if (e >= EE) return;
    int pos = atomicAdd(&g_fill[dst[e]], 1);
    int ci  = eattr[2 * e] * 3 + eattr[2 * e + 1];
    g_esort[pos] = src[e] | (ci << 20);
}

// ---------------- combo table prep ----------------
__global__ void prep_combo(const float* __restrict__ ee1,
                           const float* __restrict__ ee2) {
    int ci = blockIdx.x;
    int l  = blockIdx.y;
    int d  = threadIdx.x;
    int a0 = ci / 3, a1 = ci % 3;
    g_combo[((size_t)l * 9 + ci) * DD + d] =
        ee1[((size_t)l * 6 + a0) * DD + d] + ee2[((size_t)l * 3 + a1) * DD + d];
    if (ci == 0)
        g_self[(size_t)l * DD + d] =
            ee1[((size_t)l * 6 + 4) * DD + d] + ee2[(size_t)l * 3 * DD + d];
}

// ------- fused aggregate: inline BN, 2-way ILP edge gather ----------
__global__ void __launch_bounds__(256) agg_kernel(const float* __restrict__ combo,
                                                  const float* __restrict__ selfadd,
                                                  int useBN,
                                                  const float* __restrict__ gamma,
                                                  const float* __restrict__ beta) {
    int node = blockIdx.x * 4 + (threadIdx.x >> 6);
    int c    = threadIdx.x & 63;
    int lane = threadIdx.x & 31;
    if (node >= NN) return;
    const float4* h4 = (const float4*)g_h;
    const float4* cb4 = (const float4*)combo;

    float4 av = make_float4(1.f, 1.f, 1.f, 1.f);
    float4 cv = make_float4(0.f, 0.f, 0.f, 0.f);
    if (useBN) {
        const float invN = 1.f / (float)NN;
        float4 s = ((const float4*)g_sum)[c];
        float4 q = ((const float4*)g_sumsq)[c];
        float4 gm = ((const float4*)gamma)[c];
        float4 bt = ((const float4*)beta)[c];
        float mux = s.x * invN, muy = s.y * invN, muz = s.z * invN, muw = s.w * invN;
        av.x = gm.x * rsqrtf(q.x * invN - mux * mux + 1e-5f);
        av.y = gm.y * rsqrtf(q.y * invN - muy * muy + 1e-5f);
        av.z = gm.z * rsqrtf(q.z * invN - muz * muz + 1e-5f);
        av.w = gm.w * rsqrtf(q.w * invN - muw * muw + 1e-5f);
        cv.x = bt.x - mux * av.x;
        cv.y = bt.y - muy * av.y;
        cv.z = bt.z - muz * av.z;
        cv.w = bt.w - muw * av.w;
    }

    float4 v = h4[(size_t)node * 64 + c];
    float4 acc;
    if (useBN) {
        acc.x = fmaxf(fmaf(av.x, v.x, cv.x), 0.f);
        acc.y = fmaxf(fmaf(av.y, v.y, cv.y), 0.f);
        acc.z = fmaxf(fmaf(av.z, v.z, cv.z), 0.f);
        acc.w = fmaxf(fmaf(av.w, v.w, cv.w), 0.f);
    } else {
        acc = v;
    }
    {
        float4 t = ((const float4*)selfadd)[c];
        acc.x += t.x; acc.y += t.y; acc.z += t.z; acc.w += t.w;
    }

    int p0 = g_rowptr[node], p1 = g_rowptr[node + 1];
    int p = p0;
    int rec = (p0 + lane < p1) ? g_esort[p0 + lane] : 0;
    while (p < p1) {
        int cnt = min(32, p1 - p);
        int cur = rec;
        if (p + 32 < p1)
            rec = (p + 32 + lane < p1) ? g_esort[p + 32 + lane] : 0;
        int j = 0;
        for (; j + 2 <= cnt; j += 2) {
            int r0 = __shfl_sync(0xFFFFFFFFu, cur, j);
            int r1 = __shfl_sync(0xFFFFFFFFu, cur, j + 1);
            int s0 = r0 & 0xFFFFF, ci0 = r0 >> 20;
            int s1 = r1 & 0xFFFFF, ci1 = r1 >> 20;
            // issue both gathers before consuming (MLP=2)
            float4 w0 = h4[(size_t)s0 * 64 + c];
            float4 w1 = h4[(size_t)s1 * 64 + c];
            float4 u0 = cb4[(size_t)ci0 * 64 + c];
            float4 u1 = cb4[(size_t)ci1 * 64 + c];
            if (useBN) {
                w0.x = fmaxf(fmaf(av.x, w0.x, cv.x), 0.f);
                w0.y = fmaxf(fmaf(av.y, w0.y, cv.y), 0.f);
                w0.z = fmaxf(fmaf(av.z, w0.z, cv.z), 0.f);
                w0.w = fmaxf(fmaf(av.w, w0.w, cv.w), 0.f);
                w1.x = fmaxf(fmaf(av.x, w1.x, cv.x), 0.f);
                w1.y = fmaxf(fmaf(av.y, w1.y, cv.y), 0.f);
                w1.z = fmaxf(fmaf(av.z, w1.z, cv.z), 0.f);
                w1.w = fmaxf(fmaf(av.w, w1.w, cv.w), 0.f);
            }
            // accumulate in original sequential order (bit-exact)
            acc.x += w0.x + u0.x; acc.y += w0.y + u0.y;
            acc.z += w0.z + u0.z; acc.w += w0.w + u0.w;
            acc.x += w1.x + u1.x; acc.y += w1.y + u1.y;
            acc.z += w1.z + u1.z; acc.w += w1.w + u1.w;
        }
        if (j < cnt) {
            int r  = __shfl_sync(0xFFFFFFFFu, cur, j);
            int s  = r & 0xFFFFF;
            int ci = r >> 20;
            float4 w = h4[(size_t)s * 64 + c];
            float4 u = cb4[(size_t)ci * 64 + c];
            if (useBN) {
                w.x = fmaxf(fmaf(av.x, w.x, cv.x), 0.f);
                w.y = fmaxf(fmaf(av.y, w.y, cv.y), 0.f);
                w.z = fmaxf(fmaf(av.z, w.z, cv.z), 0.f);
                w.w = fmaxf(fmaf(av.w, w.w, cv.w), 0.f);
            }
            acc.x += w.x + u.x;
            acc.y += w.y + u.y;
            acc.z += w.z + u.z;
            acc.w += w.w + u.w;
        }
        p += cnt;
    }

    __nv_bfloat16 hx = __float2bfloat16(acc.x), hy = __float2bfloat16(acc.y);
    __nv_bfloat16 hz = __float2bfloat16(acc.z), hw = __float2bfloat16(acc.w);
    __nv_bfloat162 h0(hx, hy), h1(hz, hw);
    __nv_bfloat162 l0(__float2bfloat16(acc.x - __bfloat162float(hx)),
                      __float2bfloat16(acc.y - __bfloat162float(hy)));
    __nv_bfloat162 l1(__float2bfloat16(acc.z - __bfloat162float(hz)),
                      __float2bfloat16(acc.w - __bfloat162float(hw)));
    uint2 h, l;
    h.x = *(uint32_t*)&h0; h.y = *(uint32_t*)&h1;
    l.x = *(uint32_t*)&l0; l.y = *(uint32_t*)&l1;
    *(uint2*)(g_aggH + (size_t)node * DD + c * 4) = h;
    *(uint2*)(g_aggL + (size_t)node * DD + c * 4) = l;
}

// ---------------- weight prep ----------------
__global__ void prep_w(const float* __restrict__ W, uint4* __restrict__ dst,
                       int Nc, int ktiles) {
    int cb = blockIdx.x, kt = blockIdx.y, l = blockIdx.z;
    const float* Wl = W + (size_t)l * (ktiles * 32) * Nc;
    char* blob = (char*)dst + (((size_t)l * gridDim.x + cb) * ktiles + kt) * 16384;
    for (int e = threadIdx.x; e < 4096; e += 256) {
        int k = e >> 7, n = e & 127;
        float v = Wl[(size_t)(kt * 32 + k) * Nc + cb * 128 + n];
        __nv_bfloat16 h = __float2bfloat16(v);
        __nv_bfloat16 lo = __float2bfloat16(v - __bfloat162float(h));
        uint32_t off = k * 256 + n * 2;
        uint32_t sw = off ^ ((k & 7) << 4);
        *(__nv_bfloat16*)(blob + sw) = h;
        *(__nv_bfloat16*)(blob + 8192 + sw) = lo;
    }
}

// ====== tensor-core GEMM, bf16 3-way split, 3-stage cp.async, occ 2 ======
#define STAGE 32768
#define NSTAGE 3
#define P_AH 0
#define P_AL 8192
#define P_BH 16384
#define P_BL 24576

template <int OUT>
__global__ void __launch_bounds__(256, 2) gemm_cp(
    const __nv_bfloat16* __restrict__ AH, const __nv_bfloat16* __restrict__ AL,
    const char* __restrict__ Btiles, const float* __restrict__ bias,
    float* __restrict__ Cf, __nv_bfloat16* __restrict__ CH,
    __nv_bfloat16* __restrict__ CL, int M, int K, int Nc) {
    extern __shared__ __align__(16) char sm[];
    const int tid  = threadIdx.x;
    const int lane = tid & 31;
    const int warp = tid >> 5;
    const int wm   = warp >> 1;
    const int wn   = warp & 1;
    const int row0 = blockIdx.y * 128;
    const int col0 = blockIdx.x * 128;
    const int ktiles = K >> 5;

    if (OUT == 1 && blockIdx.x == 0 && blockIdx.y == 0) {
        g_sum[tid]   = 0.f;
        g_sumsq[tid] = 0.f;
    }

    uint32_t smbase;
    asm("{ .reg .u64 t; cvta.to.shared.u64 t, %1; cvt.u32.u64 %0, t; }"
        : "=r"(smbase) : "l"(sm));

    const int m0 = tid >> 2, kq0 = tid & 3;
    const int m1 = (tid + 256) >> 2, kq1 = (tid + 256) & 3;
    const uint32_t dA0 = (uint32_t)(m0 * 64 + kq0 * 16) ^ ((m0 & 6) << 3);
    const uint32_t dA1 = (uint32_t)(m1 * 64 + kq1 * 16) ^ ((m1 & 6) << 3);
    const uint32_t ok0 = (row0 + m0 < M) ? 16u : 0u;
    const uint32_t ok1 = (row0 + m1 < M) ? 16u : 0u;
    const __nv_bfloat16* sH0 = AH + (size_t)(row0 + m0) * K + kq0 * 8;
    const __nv_bfloat16* sH1 = AH + (size_t)(row0 + m1) * K + kq1 * 8;
    const __nv_bfloat16* sL0 = AL + (size_t)(row0 + m0) * K + kq0 * 8;
    const __nv_bfloat16* sL1 = AL + (size_t)(row0 + m1) * K + kq1 * 8;
    const char* tbase = Btiles + (size_t)blockIdx.x * ktiles * 16384;

    float acc[2][8][4];
#pragma unroll
    for (int mi = 0; mi < 2; mi++)
#pragma unroll
        for (int nt = 0; nt < 8; nt++)
#pragma unroll
            for (int q = 0; q < 4; q++) acc[mi][nt][q] = 0.f;

#define ISSUE(kt, st) do {                                                    \
        uint32_t sb = smbase + (st) * STAGE;                                  \
        int ko = (kt) * 32;                                                   \
        cpa16(sb + P_AH + dA0, sH0 + ko, ok0);                                \
        cpa16(sb + P_AH + dA1, sH1 + ko, ok1);                                \
        cpa16(sb + P_AL + dA0, sL0 + ko, ok0);                                \
        cpa16(sb + P_AL + dA1, sL1 + ko, ok1);                                \
        const char* tb = tbase + (size_t)(kt) * 16384;                        \
        cpa16(sb + P_BH + tid * 16,        tb + tid * 16, 16);                \
        cpa16(sb + P_BH + tid * 16 + 4096, tb + tid * 16 + 4096, 16);         \
        cpa16(sb + P_BL + tid * 16,        tb + 8192 + tid * 16, 16);         \
        cpa16(sb + P_BL + tid * 16 + 4096, tb + 12288 + tid * 16, 16);        \
        asm volatile("cp.async.commit_group;" ::: "memory");                  \
    } while (0)

    ISSUE(0, 0);
    if (ktiles > 1) ISSUE(1, 1);

    int stage = 0;
    for (int kt = 0; kt < ktiles; kt++) {
        if (kt + 1 < ktiles) {
            asm volatile("cp.async.wait_group 1;" ::: "memory");
        } else {
            asm volatile("cp.async.wait_group 0;" ::: "memory");
        }
        __syncthreads();

        if (kt + 2 < ktiles) {
            int nst = stage + 2;
            if (nst >= NSTAGE) nst -= NSTAGE;
            ISSUE(kt + 2, nst);
        }

        const uint32_t cbase = smbase + stage * STAGE;
#pragma unroll
        for (int ks = 0; ks < 2; ks++) {
            uint32_t a_h[2][4], a_l[2][4];
#pragma unroll
            for (int mi = 0; mi < 2; mi++) {
                int m = wm * 32 + mi * 16 + (lane & 15);
                int k = ks * 16 + (lane >> 4) * 8;
                uint32_t byte = (uint32_t)(m * 64 + k * 2) ^ ((m & 6) << 3);
                ldsm4(a_h[mi], cbase + P_AH + byte);
                ldsm4(a_l[mi], cbase + P_AL + byte);
            }
#pragma unroll
            for (int nj = 0; nj < 4; nj++) {
                int k = ks * 16 + (lane & 15);
                int n = wn * 64 + nj * 16 + (lane >> 4) * 8;
                uint32_t byte = (uint32_t)(k * 256 + n * 2) ^ ((k & 7) << 4);
                uint32_t bh[4], bl[4];
                ldsm4t(bh, cbase + P_BH + byte);
                ldsm4t(bl, cbase + P_BL + byte);
#pragma unroll
                for (int mi = 0; mi < 2; mi++) {
                    mma16816(acc[mi][2 * nj],     a_h[mi], bh[0], bh[1]);
                    mma16816(acc[mi][2 * nj],     a_h[mi], bl[0], bl[1]);
                    mma16816(acc[mi][2 * nj],     a_l[mi], bh[0], bh[1]);
                    mma16816(acc[mi][2 * nj + 1], a_h[mi], bh[2], bh[3]);
                    mma16816(acc[mi][2 * nj + 1], a_h[mi], bl[2], bl[3]);
                    mma16816(acc[mi][2 * nj + 1], a_l[mi], bh[2], bh[3]);
                }
            }
        }
        if (++stage >= NSTAGE) stage = 0;
    }
#undef ISSUE

    if (OUT == 1) {
#pragma unroll
        for (int mi = 0; mi < 2; mi++) {
            int r0 = row0 + wm * 32 + mi * 16 + (lane >> 2);
#pragma unroll
            for (int nt = 0; nt < 8; nt++) {
                int c = col0 + wn * 64 + nt * 8 + (lane & 3) * 2;
                float2 bv = *(const float2*)(bias + c);
                float* a4 = acc[mi][nt];
#pragma unroll
                for (int half = 0; half < 2; half++) {
                    int r = r0 + half * 8;
                    if (r < M) {
                        float v0 = fmaxf(a4[2 * half + 0] + bv.x, 0.f);
                        float v1 = fmaxf(a4[2 * half + 1] + bv.y, 0.f);
                        __nv_bfloat16 h0 = __float2bfloat16(v0);
                        __nv_bfloat16 h1 = __float2bfloat16(v1);
                        __nv_bfloat162 hp(h0, h1);
                        __nv_bfloat162 lp(__float2bfloat16(v0 - __bfloat162float(h0)),
                                          __float2bfloat16(v1 - __bfloat162float(h1)));
                        *(__nv_bfloat162*)(CH + (size_t)r * Nc + c) = hp;
                        *(__nv_bfloat162*)(CL + (size_t)r * Nc + c) = lp;
                    }
                }
            }
        }
    } else {
        float cs[16], cq[16];
#pragma unroll
        for (int j = 0; j < 16; j++) { cs[j] = 0.f; cq[j] = 0.f; }
#pragma unroll
        for (int mi = 0; mi < 2; mi++) {
            int r0 = row0 + wm * 32 + mi * 16 + (lane >> 2);
#pragma unroll
            for (int nt = 0; nt < 8; nt++) {
                int c = col0 + wn * 64 + nt * 8 + (lane & 3) * 2;
                float2 bv = *(const float2*)(bias + c);
                float* a4 = acc[mi][nt];
#pragma unroll
                for (int half = 0; half < 2; half++) {
                    int r = r0 + half * 8;
                    if (r < M) {
                        float v0 = a4[2 * half + 0] + bv.x;
                        float v1 = a4[2 * half + 1] + bv.y;
                        float2 o; o.x = v0; o.y = v1;
                        *(float2*)(Cf + (size_t)r * Nc + c) = o;
                        cs[nt * 2 + 0] += v0; cq[nt * 2 + 0] += v0 * v0;
                        cs[nt * 2 + 1] += v1; cq[nt * 2 + 1] += v1 * v1;
                    }
                }
            }
        }
#pragma unroll
        for (int j = 0; j < 16; j++) {
#pragma unroll
            for (int msk = 4; msk <= 16; msk <<= 1) {
                cs[j] += __shfl_xor_sync(0xFFFFFFFF, cs[j], msk);
                cq[j] += __shfl_xor_sync(0xFFFFFFFF, cq[j], msk);
            }
        }
        float* ssum = (float*)sm;
        float* ssq  = ssum + 128;
        __syncthreads();
        if (tid < 128) { ssum[tid] = 0.f; ssq[tid] = 0.f; }
        __syncthreads();
        if ((lane >> 2) == 0) {
#pragma unroll
            for (int j = 0; j < 16; j++) {
                int cl = wn * 64 + (j >> 1) * 8 + (lane & 3) * 2 + (j & 1);
                atomicAdd(&ssum[cl], cs[j]);
                atomicAdd(&ssq[cl],  cq[j]);
            }
        }
        __syncthreads();
        if (tid < 128) {
            atomicAdd(&g_sum[col0 + tid],   ssum[tid]);
            atomicAdd(&g_sumsq[col0 + tid], ssq[tid]);
        }
    }
}

// ---------------- small GEMM (head MLP), optional per-row scale ----------
template <int RELU>
__global__ void __launch_bounds__(256) gemm_bias(const float* __restrict__ A,
                                                 const float* __restrict__ B,
                                                 const float* __restrict__ bias,
                                                 float* __restrict__ C,
                                                 int M, int K, int Nc,
                                                 const float* __restrict__ rowcnt) {
    __shared__ float As[16][64];
    __shared__ float Bs[16][64];

    int tid  = threadIdx.x;
    int row0 = blockIdx.y * 64;
    int col0 = blockIdx.x * 64;
    int ty   = tid >> 4;
    int tx   = tid & 15;

    int ar = tid >> 2;
    int ak = (tid & 3) * 4;
    int bk = tid >> 4;
    int bc = (tid & 15) * 4;

    float acc[4][4];
#pragma unroll
    for (int i = 0; i < 4; i++)
#pragma unroll
        for (int j = 0; j < 4; j++) acc[i][j] = 0.f;

    int arow = row0 + ar;
    int bcol = col0 + bc;
    float rs = 1.f;
    if (rowcnt && arow < M) rs = 1.f / fmaxf(rowcnt[arow], 1.f);

    for (int k0 = 0; k0 < K; k0 += 16) {
        float4 av = make_float4(0.f, 0.f, 0.f, 0.f);
        if (arow < M)
            av = *(const float4*)(A + (size_t)arow * K + k0 + ak);
        As[ak + 0][ar] = av.x * rs;
        As[ak + 1][ar] = av.y * rs;
        As[ak + 2][ar] = av.z * rs;
        As[ak + 3][ar] = av.w * rs;

        float4 bv = make_float4(0.f, 0.f, 0.f, 0.f);
        if (bcol < Nc)
            bv = *(const float4*)(B + (size_t)(k0 + bk) * Nc + bcol);
        *(float4*)(&Bs[bk][bc]) = bv;

        __syncthreads();
#pragma unroll
        for (int k = 0; k < 16; k++) {
            float4 a4 = *(const float4*)(&As[k][ty * 4]);
            float4 b4 = *(const float4*)(&Bs[k][tx * 4]);
            float a[4] = {a4.x, a4.y, a4.z, a4.w};
            float b[4] = {b4.x, b4.y, b4.z, b4.w};
#pragma unroll
            for (int i = 0; i < 4; i++)
#pragma unroll
                for (int j = 0; j < 4; j++)
                    acc[i][j] = fmaf(a[i], b[j], acc[i][j]);
        }
        __syncthreads();
    }

#pragma unroll
    for (int i = 0; i < 4; i++) {
        int r = row0 + ty * 4 + i;
        if (r < M) {
#pragma unroll
            for (int j = 0; j < 4; j++) {
                int c = col0 + tx * 4 + j;
                if (c < Nc) {
                    float v = acc[i][j] + bias[c];
                    if (RELU) v = fmaxf(v, 0.f);
                    C[(size_t)r * Nc + c] = v;
                }
            }
        }
    }
}

// ---------------- pooling (inline last-layer BN affine, no relu) ----------
__global__ void count_kernel(const int* __restrict__ batch) {
    int i = blockIdx.x * 256 + threadIdx.x;
    if (i < NN) atomicAdd(&g_cnt[batch[i]], 1.f);
}

__global__ void pool_scatter_kernel(const int* __restrict__ batch,
                                    const float* __restrict__ gamma,
                                    const float* __restrict__ beta) {
    int n = blockIdx.x * 4 + (threadIdx.x >> 6);
    int c = threadIdx.x & 63;
    if (n >= NN) return;
    const float invN = 1.f / (float)NN;
    float4 s = ((const float4*)g_sum)[c];
    float4 q = ((const float4*)g_sumsq)[c];
    float4 gm = ((const float4*)gamma)[c];
    float4 bt = ((const float4*)beta)[c];
    float mux = s.x * invN, muy = s.y * invN, muz = s.z * invN, muw = s.w * invN;
    float ax = gm.x * rsqrtf(q.x * invN - mux * mux + 1e-5f);
    float ay = gm.y * rsqrtf(q.y * invN - muy * muy + 1e-5f);
    float az = gm.z * rsqrtf(q.z * invN - muz * muz + 1e-5f);
    float aw = gm.w * rsqrtf(q.w * invN - muw * muw + 1e-5f);
    float cx = bt.x - mux * ax, cy = bt.y - muy * ay;
    float cz = bt.z - muz * az, cw = bt.w - muw * aw;

    int g = batch[n];
    float4 v = ((const float4*)(g_h + (size_t)n * DD))[c];
    v.x = fmaf(ax, v.x, cx);
    v.y = fmaf(ay, v.y, cy);
    v.z = fmaf(az, v.z, cz);
    v.w = fmaf(aw, v.w, cw);
    red_add_v4(g_mol + (size_t)g * DD + c * 4, v);
}

// ---------------- head final ----------------
__global__ void head_final_kernel(const float* __restrict__ w,
                                  const float* __restrict__ b,
                                  float* __restrict__ out) {
    int g = blockIdx.x * 256 + threadIdx.x;
    if (g >= GG) return;
    float acc = b[0];
#pragma unroll
    for (int k = 0; k < 32; k++)
        acc = fmaf(g_z2[g * 32 + k], w[k], acc);
    out[g] = acc;
}

// ---------------- launch ----------------
extern "C" void kernel_launch(void* const* d_in, const int* in_sizes, int n_in,
                              void* d_out, int out_size) {
    const float* x          = (const float*)d_in[0];
    const int*   edge_index = (const int*)d_in[1];
    const int*   edge_attr  = (const int*)d_in[2];
    const int*   batch      = (const int*)d_in[3];
    const float* embW       = (const float*)d_in[4];
    const float* embB       = (const float*)d_in[5];
    const float* ee1        = (const float*)d_in[6];
    const float* ee2        = (const float*)d_in[7];
    const float* W1         = (const float*)d_in[8];
    const float* b1         = (const float*)d_in[9];
    const float* W2         = (const float*)d_in[10];
    const float* b2         = (const float*)d_in[11];
    const float* bn_g       = (const float*)d_in[12];
    const float* bn_b       = (const float*)d_in[13];
    const float* hW0 = (const float*)d_in[14];
    const float* hb0 = (const float*)d_in[15];
    const float* hW1 = (const float*)d_in[16];
    const float* hb1 = (const float*)d_in[17];
    const float* hW2 = (const float*)d_in[18];
    const float* hb2 = (const float*)d_in[19];
    const float* hW3 = (const float*)d_in[20];
    const float* hb3 = (const float*)d_in[21];
    const float* hWo = (const float*)d_in[22];
    const float* hbo = (const float*)d_in[23];
    float* out = (float*)d_out;

    const int* src = edge_index;
    const int* dst = edge_index + EE;

    float *p_h, *p_mol, *p_z1, *p_z2, *p_combo, *p_self, *p_cnt;
    __nv_bfloat16 *p_aggH, *p_aggL, *p_tH, *p_tL;
    uint4 *p_W1t, *p_W2t;
    cudaGetSymbolAddress((void**)&p_h,     g_h);
    cudaGetSymbolAddress((void**)&p_mol,   g_mol);
    cudaGetSymbolAddress((void**)&p_z1,    g_z1);
    cudaGetSymbolAddress((void**)&p_z2,    g_z2);
    cudaGetSymbolAddress((void**)&p_aggH,  g_aggH);
    cudaGetSymbolAddress((void**)&p_aggL,  g_aggL);
    cudaGetSymbolAddress((void**)&p_tH,    g_tH);
    cudaGetSymbolAddress((void**)&p_tL,    g_tL);
    cudaGetSymbolAddress((void**)&p_W1t,   g_W1t);
    cudaGetSymbolAddress((void**)&p_W2t,   g_W2t);
    cudaGetSymbolAddress((void**)&p_combo, g_combo);
    cudaGetSymbolAddress((void**)&p_self,  g_self);
    cudaGetSymbolAddress((void**)&p_cnt,   g_cnt);

    static int smem_set = 0;
    if (!smem_set) {
        cudaFuncSetAttribute(gemm_cp<1>, cudaFuncAttributeMaxDynamicSharedMemorySize, NSTAGE * STAGE);
        cudaFuncSetAttribute(gemm_cp<0>, cudaFuncAttributeMaxDynamicSharedMemorySize, NSTAGE * STAGE);
        smem_set = 1;
    }

    const int rowBlocks = (NN + 127) / 128;

    // weight prep + combo tables + CSR build (once per call)
    prep_w<<<dim3(4, 8, 5),  256>>>(W1, p_W1t, 512, 8);
    prep_w<<<dim3(2, 16, 5), 256>>>(W2, p_W2t, 256, 16);
    prep_combo<<<dim3(9, 5), 256>>>(ee1, ee2);
    init_kernel<<<(GG * DD + 255) / 256, 256>>>();
    hist_kernel<<<(EE + 255) / 256, 256>>>(dst);
    scan_kernel<<<1, 1024>>>();
    fill_kernel<<<(EE + 255) / 256, 256>>>(src, dst, edge_attr);
    count_kernel<<<(NN + 255) / 256, 256>>>(batch);

    embed_kernel<<<(NN + 63) / 64, 256>>>(x, embW, embB);

    for (int l = 0; l < LL; l++) {
        agg_kernel<<<(NN + 3) / 4, 256>>>(p_combo + (size_t)l * 9 * DD,
                                          p_self + (size_t)l * DD,
                                          l > 0 ? 1 : 0,
                                          bn_g + (size_t)(l > 0 ? l - 1 : 0) * DD,
                                          bn_b + (size_t)(l > 0 ? l - 1 : 0) * DD);
        gemm_cp<1><<<dim3(4, rowBlocks), 256, NSTAGE * STAGE>>>(
            p_aggH, p_aggL, (const char*)p_W1t + (size_t)l * 4 * 8 * 16384,
            b1 + (size_t)l * 2 * DD, nullptr, p_tH, p_tL, NN, DD, 2 * DD);
        gemm_cp<0><<<dim3(2, rowBlocks), 256, NSTAGE * STAGE>>>(
            p_tH, p_tL, (const char*)p_W2t + (size_t)l * 2 * 16 * 16384,
            b2 + (size_t)l * DD, p_h, nullptr, nullptr, NN, 2 * DD, DD);
    }

    pool_scatter_kernel<<<(NN + 3) / 4, 256>>>(batch,
                                               bn_g + (size_t)(LL - 1) * DD,
                                               bn_b + (size_t)(LL - 1) * DD);

    // head MLP: mean division folded into first gemm's A-load
    gemm_bias<1><<<dim3(4, (GG + 63) / 64), 256>>>(p_mol, hW0, hb0, p_z1, GG, 256, 256, p_cnt);
    gemm_bias<1><<<dim3(2, (GG + 63) / 64), 256>>>(p_z1,  hW1, hb1, p_z2, GG, 256, 128, nullptr);
    gemm_bias<1><<<dim3(1, (GG + 63) / 64), 256>>>(p_z2,  hW2, hb2, p_z1, GG, 128, 64, nullptr);
    gemm_bias<1><<<dim3(1, (GG + 63) / 64), 256>>>(p_z1,  hW3, hb3, p_z2, GG, 64, 32, nullptr);
    head_final_kernel<<<(GG + 255) / 256, 256>>>(hWo, hbo, out);
}